// round 2
// baseline (speedup 1.0000x reference)
#include <cuda_runtime.h>
#include <math.h>

#define NTN  65536      // total nodes
#define ETOT 524288     // total edges
#define NB   32         // graphs
#define NH   128        // hidden/feature dim
#define CAP  64         // max in-degree capacity (Poisson(8), P(>=40) ~ 1e-16)

// ---------------- device scratch (static, allocation-free) ----------------
__device__ float d_h[NTN * NH];      // current features
__device__ float d_hw[NTN * NH];     // GEMM output h@W
__device__ float d_sclin[NTN];       // h@Wp (score linear part)
__device__ float d_score[NTN];
__device__ float d_dinv[NTN];
__device__ float d_nmask[NTN];
__device__ int   d_cnt[NTN];
__device__ int   d_adj[NTN * CAP];   // CSR-by-dst, fixed capacity
__device__ int   d_listA[NTN];       // ping-pong active-node lists
__device__ int   d_listB[NTN];
__device__ float d_gacc[NB * 256];   // readout accumulator x1+x2+x3

__device__ __forceinline__ const int* sel_list(int s) { return s ? d_listB : d_listA; }

// ---------------- init ----------------
__global__ void k_init() {
    int i = blockIdx.x * blockDim.x + threadIdx.x;
    if (i < NTN) { d_cnt[i] = 0; d_nmask[i] = 1.f; d_listA[i] = i; }
    if (i < NB * 256) d_gacc[i] = 0.f;
}

// ---------------- CSR build: histogram fill ----------------
__global__ void k_fill(const int* __restrict__ ei) {
    int e = blockIdx.x * blockDim.x + threadIdx.x;
    if (e >= ETOT) return;
    int s = ei[e];
    int d = ei[ETOT + e];
    int p = atomicAdd(&d_cnt[d], 1);
    if (p < CAP) d_adj[d * CAP + p] = s;
}

// sort each adjacency list -> bitwise-deterministic accumulation order
__global__ void k_sortadj() {
    int v = blockIdx.x * blockDim.x + threadIdx.x;
    if (v >= NTN) return;
    int n = d_cnt[v]; if (n > CAP) n = CAP;
    int* a = d_adj + v * CAP;
    for (int i = 1; i < n; i++) {
        int key = a[i]; int j = i - 1;
        while (j >= 0 && a[j] > key) { a[j + 1] = a[j]; j--; }
        a[j + 1] = key;
    }
}

// ---------------- degree / dinv ----------------
__global__ void k_dinv() {
    int v = blockIdx.x * blockDim.x + threadIdx.x;
    if (v >= NTN) return;
    if (d_nmask[v] == 0.f) { d_dinv[v] = 0.f; return; }
    int n = d_cnt[v]; if (n > CAP) n = CAP;
    const int* a = d_adj + v * CAP;
    float deg = 1.f;                       // self-loop (nmask[v]=1)
    for (int i = 0; i < n; i++) deg += d_nmask[a[i]];
    d_dinv[v] = rsqrtf(deg);
}

// ---------------- indexed 128x128 GEMM: d_hw[list[r]] = A[list[r]] @ W ----------------
__global__ void __launch_bounds__(256, 2) k_gemm(const float* __restrict__ Aext,
                                                 const float* __restrict__ W,
                                                 int lsel, int useInternal) {
    __shared__ float As[32][132];
    __shared__ float Bs[32][128];
    const float* A = useInternal ? d_h : Aext;
    const int* list = sel_list(lsel);
    int tid = threadIdx.x;
    int tx = tid & 15, ty = tid >> 4;
    int mbase = blockIdx.x * 128;

    float acc[8][8];
#pragma unroll
    for (int i = 0; i < 8; i++)
#pragma unroll
        for (int j = 0; j < 8; j++) acc[i][j] = 0.f;

    for (int k0 = 0; k0 < 128; k0 += 32) {
#pragma unroll
        for (int i = 0; i < 4; i++) {
            int q = tid + i * 256;          // 0..1023 float4 ids
            int m = q >> 3;                 // row within tile
            int kk = (q & 7) << 2;          // k offset within chunk
            int row = list[mbase + m];
            float4 v = *(const float4*)(A + (size_t)row * NH + k0 + kk);
            As[kk + 0][m] = v.x; As[kk + 1][m] = v.y;
            As[kk + 2][m] = v.z; As[kk + 3][m] = v.w;
        }
#pragma unroll
        for (int i = 0; i < 4; i++) {
            int q = tid + i * 256;
            int kk = q >> 5;
            int n4 = (q & 31) << 2;
            *(float4*)&Bs[kk][n4] = *(const float4*)(W + (size_t)(k0 + kk) * NH + n4);
        }
        __syncthreads();
#pragma unroll
        for (int kk = 0; kk < 32; kk++) {
            float a[8], b[8];
#pragma unroll
            for (int i = 0; i < 8; i++) a[i] = As[kk][ty * 8 + i];
#pragma unroll
            for (int j = 0; j < 8; j++) b[j] = Bs[kk][tx * 8 + j];
#pragma unroll
            for (int i = 0; i < 8; i++)
#pragma unroll
                for (int j = 0; j < 8; j++) acc[i][j] += a[i] * b[j];
        }
        __syncthreads();
    }
#pragma unroll
    for (int i = 0; i < 8; i++) {
        int row = list[mbase + ty * 8 + i];
        float* o = d_hw + (size_t)row * NH + tx * 8;
        *(float4*)o       = make_float4(acc[i][0], acc[i][1], acc[i][2], acc[i][3]);
        *(float4*)(o + 4) = make_float4(acc[i][4], acc[i][5], acc[i][6], acc[i][7]);
    }
}

// ---------------- GCN aggregation + bias + relu, fused score-linear (h@Wp) ----------------
// warp per active node: out[v] = relu(dinv[v]*sum_u dinv[u]*hw[u] + dinv[v]^2*hw[v] + b)
__global__ void k_agg(const float* __restrict__ b, const float* __restrict__ Wp,
                      int lsel, int A) {
    int w = (blockIdx.x * blockDim.x + threadIdx.x) >> 5;
    int lane = threadIdx.x & 31;
    if (w >= A) return;
    int v = sel_list(lsel)[w];
    float dv = d_dinv[v];
    float4 self = ((const float4*)(d_hw + (size_t)v * NH))[lane];
    float4 na = make_float4(0.f, 0.f, 0.f, 0.f);
    int n = d_cnt[v]; if (n > CAP) n = CAP;
    const int* adj = d_adj + v * CAP;
    for (int i = 0; i < n; i++) {
        int u = adj[i];
        float du = d_dinv[u];
        if (du != 0.f) {
            float4 hu = ((const float4*)(d_hw + (size_t)u * NH))[lane];
            na.x += du * hu.x; na.y += du * hu.y;
            na.z += du * hu.z; na.w += du * hu.w;
        }
    }
    float4 b4 = ((const float4*)b)[lane];
    float dv2 = dv * dv;
    float4 r;
    r.x = fmaxf(dv * na.x + dv2 * self.x + b4.x, 0.f);
    r.y = fmaxf(dv * na.y + dv2 * self.y + b4.y, 0.f);
    r.z = fmaxf(dv * na.z + dv2 * self.z + b4.z, 0.f);
    r.w = fmaxf(dv * na.w + dv2 * self.w + b4.w, 0.f);
    ((float4*)(d_h + (size_t)v * NH))[lane] = r;
    // fused score linear: sclin[v] = h_new[v] . Wp
    float4 wp = ((const float4*)Wp)[lane];
    float s = r.x * wp.x + r.y * wp.y + r.z * wp.z + r.w * wp.w;
#pragma unroll
    for (int o = 16; o > 0; o >>= 1) s += __shfl_down_sync(0xffffffffu, s, o);
    if (lane == 0) d_sclin[v] = s;
}

// ---------------- score GCN aggregation (scalar) ----------------
__global__ void k_score(const float* __restrict__ bp, int lsel, int A) {
    int i = blockIdx.x * blockDim.x + threadIdx.x;
    if (i >= A) return;
    int v = sel_list(lsel)[i];
    float dv = d_dinv[v];
    int n = d_cnt[v]; if (n > CAP) n = CAP;
    const int* adj = d_adj + v * CAP;
    float acc = 0.f;
    for (int j = 0; j < n; j++) {
        int u = adj[j];
        float du = d_dinv[u];
        if (du != 0.f) acc += du * d_sclin[u];
    }
    d_score[v] = dv * acc + dv * dv * d_sclin[v] + bp[0];
}

// ---------------- per-graph top-k via bitonic sort of (score, pos) keys ----------------
__global__ void k_topk(int oldSel, int A, int k) {
    __shared__ unsigned long long keys[2048];
    int g = blockIdx.x, tid = threadIdx.x;
    const int* oldl = sel_list(oldSel);
    int* newl = oldSel ? d_listA : d_listB;
    for (int j = tid; j < 2048; j += 1024) {
        unsigned long long key = 0ull;
        if (j < A) {
            int v = oldl[g * A + j];
            unsigned bb = __float_as_uint(d_score[v]);
            bb = (bb & 0x80000000u) ? ~bb : (bb | 0x80000000u);   // sortable float
            key = ((unsigned long long)bb << 32) | (unsigned)(~j); // tie-break: lower pos wins
        }
        keys[j] = key;
    }
    for (int ks = 2; ks <= 2048; ks <<= 1)
        for (int jj = ks >> 1; jj > 0; jj >>= 1) {
            __syncthreads();
            for (int t = tid; t < 2048; t += 1024) {
                int ixj = t ^ jj;
                if (ixj > t) {
                    bool asc = ((t & ks) == 0);
                    unsigned long long a = keys[t], b = keys[ixj];
                    if (asc ? (a > b) : (a < b)) { keys[t] = b; keys[ixj] = a; }
                }
            }
        }
    __syncthreads();
    for (int j = tid; j < A; j += 1024) {
        unsigned long long kv = keys[2047 - j];          // rank j (0 = largest)
        int pos = (int)(~(unsigned)kv);
        int v = oldl[g * A + pos];
        if (j < k) newl[g * k + j] = v;
        else       d_nmask[v] = 0.f;
    }
}

// ---------------- fused h *= tanh(score) on kept nodes + readout (max, mean) ----------------
__global__ void k_readout(int sel, int k) {
    __shared__ float smx[8][128], ssm[8][128];
    int g = blockIdx.x;
    int f = threadIdx.x & 127;
    int r = threadIdx.x >> 7;
    const int* lst = sel_list(sel);
    float mx = -3.402823466e+38f, sm = 0.f;
    for (int j = r; j < k; j += 8) {
        int v = lst[g * k + j];
        float t = tanhf(d_score[v]);
        float val = d_h[(size_t)v * NH + f] * t;
        d_h[(size_t)v * NH + f] = val;     // becomes next layer input
        mx = fmaxf(mx, val); sm += val;
    }
    smx[r][f] = mx; ssm[r][f] = sm;
    __syncthreads();
    if (r == 0) {
        for (int q = 1; q < 8; q++) { mx = fmaxf(mx, smx[q][f]); sm += ssm[q][f]; }
        d_gacc[g * 256 + f]       += mx;
        d_gacc[g * 256 + 128 + f] += sm / (float)k;
    }
}

// ---------------- MLP head + log_softmax ----------------
__global__ void k_mlp(const float* __restrict__ W1, const float* __restrict__ B1,
                      const float* __restrict__ W2, const float* __restrict__ B2,
                      const float* __restrict__ W3, const float* __restrict__ B3,
                      float* __restrict__ out) {
    __shared__ float gv[256], l1[128], l2[64], lg[10];
    int g = blockIdx.x, t = threadIdx.x;
    gv[t] = d_gacc[g * 256 + t];
    gv[t + 128] = d_gacc[g * 256 + 128 + t];
    __syncthreads();
    float a = B1[t];
    for (int i = 0; i < 256; i++) a += gv[i] * W1[i * 128 + t];
    l1[t] = fmaxf(a, 0.f);
    __syncthreads();
    if (t < 64) {
        float c = B2[t];
        for (int i = 0; i < 128; i++) c += l1[i] * W2[i * 64 + t];
        l2[t] = fmaxf(c, 0.f);
    }
    __syncthreads();
    if (t < 10) {
        float c = B3[t];
        for (int i = 0; i < 64; i++) c += l2[i] * W3[i * 10 + t];
        lg[t] = c;
    }
    __syncthreads();
    if (t == 0) {
        float m = lg[0];
        for (int c = 1; c < 10; c++) m = fmaxf(m, lg[c]);
        float s = 0.f;
        for (int c = 0; c < 10; c++) s += expf(lg[c] - m);
        float L = m + logf(s);
        for (int c = 0; c < 10; c++) out[g * 10 + c] = lg[c] - L;
    }
}

// ---------------- launch ----------------
extern "C" void kernel_launch(void* const* d_in, const int* in_sizes, int n_in,
                              void* d_out, int out_size) {
    (void)in_sizes; (void)n_in; (void)out_size;
    const float* x   = (const float*)d_in[0];
    const int*   ei  = (const int*)d_in[1];
    const float* W1  = (const float*)d_in[3];  const float* b1  = (const float*)d_in[4];
    const float* Wp1 = (const float*)d_in[5];  const float* bp1 = (const float*)d_in[6];
    const float* W2  = (const float*)d_in[7];  const float* b2  = (const float*)d_in[8];
    const float* Wp2 = (const float*)d_in[9];  const float* bp2 = (const float*)d_in[10];
    const float* W3  = (const float*)d_in[11]; const float* b3  = (const float*)d_in[12];
    const float* Wp3 = (const float*)d_in[13]; const float* bp3 = (const float*)d_in[14];
    const float* L1W = (const float*)d_in[15]; const float* L1b = (const float*)d_in[16];
    const float* L2W = (const float*)d_in[17]; const float* L2b = (const float*)d_in[18];
    const float* L3W = (const float*)d_in[19]; const float* L3b = (const float*)d_in[20];
    float* out = (float*)d_out;

    // setup: masks, identity list, CSR
    k_init<<<NTN / 256, 256>>>();
    k_fill<<<ETOT / 256, 256>>>(ei);
    k_sortadj<<<NTN / 256, 256>>>();

    // ---- layer 1: active = 65536 (listA identity), keep K1=1024/graph -> listB ----
    k_dinv<<<NTN / 256, 256>>>();
    k_gemm<<<65536 / 128, 256>>>(x, W1, 0, 0);
    k_agg<<<65536 / 8, 256>>>(b1, Wp1, 0, 65536);
    k_score<<<65536 / 256, 256>>>(bp1, 0, 65536);
    k_topk<<<NB, 1024>>>(0, 2048, 1024);
    k_readout<<<NB, 1024>>>(1, 1024);

    // ---- layer 2: active = 32768 (listB), keep K2=512/graph -> listA ----
    k_dinv<<<NTN / 256, 256>>>();
    k_gemm<<<32768 / 128, 256>>>(nullptr, W2, 1, 1);
    k_agg<<<32768 / 8, 256>>>(b2, Wp2, 1, 32768);
    k_score<<<32768 / 256, 256>>>(bp2, 1, 32768);
    k_topk<<<NB, 1024>>>(1, 1024, 512);
    k_readout<<<NB, 1024>>>(0, 512);

    // ---- layer 3: active = 16384 (listA), keep K3=256/graph -> listB ----
    k_dinv<<<NTN / 256, 256>>>();
    k_gemm<<<16384 / 128, 256>>>(nullptr, W3, 0, 1);
    k_agg<<<16384 / 8, 256>>>(b3, Wp3, 0, 16384);
    k_score<<<16384 / 256, 256>>>(bp3, 0, 16384);
    k_topk<<<NB, 1024>>>(0, 512, 256);
    k_readout<<<NB, 1024>>>(1, 256);

    // ---- MLP head ----
    k_mlp<<<NB, 128>>>(L1W, L1b, L2W, L2b, L3W, L3b, out);
}